// round 14
// baseline (speedup 1.0000x reference)
#include <cuda_runtime.h>
#include <cuda_fp16.h>
#include <float.h>
#include <math.h>

// CapsuleConv2d: B=2, Cin=128, H=W=32, weight [O=16,L=16,M=16,3,3]
// 1 CTA per (b,h,w), 256 threads (8 warps), single routing pass.
// PRIORS ON TENSOR CORES: per p, C_p[256(ol) x 8(g)] = W_p[256x16] * XS_p[16x8]
//   m16n8k16; warp w owns ol-tiles {2w, 2w+1}. A-fragments precomputed (g_wfrag),
//   B-fragments straight from fp16 patch. C stored as PAIRED half2 (ol, ol+8)
//   at permuted column positions -> STS.32, half the scatter ops.
// ROUTING: 1 column/thread; the pair permutation is transparent to the math
//   (elementwise in k); only the output column index is remapped.

__device__ uint4 g_wfrag[9 * 16 * 32];  // [(p*16+tile)*32 + lane] = {a0,a1,a2,a3}

__global__ void wt_frag(const float* __restrict__ w) {
    int idx = blockIdx.x * 256 + threadIdx.x;   // 4608 total
    if (idx >= 4608) return;
    int p    = idx >> 9;          // 0..8
    int tile = (idx >> 5) & 15;   // ol tile
    int lane = idx & 31;
    int gid  = lane >> 2;         // row group
    int kb   = (lane & 3) * 2;    // col base (k)
    const int base = tile * 16;
    auto W = [&](int r, int k) { return w[((base + r) * 16 + k) * 9 + p]; };
    __half2 a0 = __floats2half2_rn(W(gid,     kb),     W(gid,     kb + 1));
    __half2 a1 = __floats2half2_rn(W(gid + 8, kb),     W(gid + 8, kb + 1));
    __half2 a2 = __floats2half2_rn(W(gid,     kb + 8), W(gid,     kb + 9));
    __half2 a3 = __floats2half2_rn(W(gid + 8, kb + 8), W(gid + 8, kb + 9));
    uint4 o;
    o.x = *reinterpret_cast<unsigned*>(&a0);
    o.y = *reinterpret_cast<unsigned*>(&a1);
    o.z = *reinterpret_cast<unsigned*>(&a2);
    o.w = *reinterpret_cast<unsigned*>(&a3);
    g_wfrag[idx] = o;
}

#define USTRIDE_P 132   // su row stride in half2 pairs (528 B)

__global__ __launch_bounds__(256, 2)
void capsule_kernel(const float* __restrict__ x, float* __restrict__ out) {
    extern __shared__ __align__(16) __half smemh[];
    __half* xsh = smemh;                                          // [1152] patch fp16
    __half2* su2 = reinterpret_cast<__half2*>(smemh + 1152);      // [72*USTRIDE_P]

    const unsigned FULL = 0xffffffffu;
    const int tid = threadIdx.x;
    const int lane = tid & 15;       // routing lane in 16-group
    const int go  = tid >> 4;        // o group (0..15)
    const int wid = tid >> 5;        // warp id (0..7)
    const int l32 = tid & 31;
    const int gid = l32 >> 2;        // mma row group
    const int kb  = (l32 & 3) * 2;   // mma k/g base
    const int bid = blockIdx.x;
    const int b = bid >> 10;
    const int h = (bid >> 5) & 31;
    const int w = bid & 31;

    // Stage 3x3 patch (zero-padded) as fp16: 9 pixels x 128 channels
    for (int idx = tid; idx < 9 * 128; idx += 256) {
        int p = idx >> 7;
        int c = idx & 127;
        int hh = h + p / 3 - 1;
        int ww = w + p % 3 - 1;
        float v = 0.f;
        if ((unsigned)hh < 32u && (unsigned)ww < 32u)
            v = x[((b * 128 + c) * 32 + hh) * 32 + ww];
        xsh[idx] = __float2half_rn(v);
    }
    __syncthreads();

    // ---- priors via tensor cores; warp handles tiles {2*wid, 2*wid+1} ----
#pragma unroll
    for (int p = 0; p < 9; p++) {
        unsigned b0 = *reinterpret_cast<const unsigned*>(&xsh[p * 128 + gid * 16 + kb]);
        unsigned b1 = *reinterpret_cast<const unsigned*>(&xsh[p * 128 + gid * 16 + kb + 8]);
#pragma unroll
        for (int tt = 0; tt < 2; tt++) {
            int tile = wid * 2 + tt;
            uint4 af = g_wfrag[(p * 16 + tile) * 32 + l32];
            float d0, d1, d2, d3;
            asm volatile(
                "mma.sync.aligned.m16n8k16.row.col.f32.f16.f16.f32 "
                "{%0,%1,%2,%3}, {%4,%5,%6,%7}, {%8,%9}, {%10,%11,%12,%13};"
                : "=f"(d0), "=f"(d1), "=f"(d2), "=f"(d3)
                : "r"(af.x), "r"(af.y), "r"(af.z), "r"(af.w),
                  "r"(b0), "r"(b1),
                  "f"(0.f), "f"(0.f), "f"(0.f), "f"(0.f));
            // d0=(ol0, g=kb) d1=(ol0, kb+1) d2=(ol0+8, kb) d3=(ol0+8, kb+1)
            // paired store: pair position gid holds (ol0, ol0+8)
            int n0 = kb * 9 + p;
            int pp = tile * 8 + gid;
            su2[n0 * USTRIDE_P + pp]       = __floats2half2_rn(d0, d2);
            su2[(n0 + 9) * USTRIDE_P + pp] = __floats2half2_rn(d1, d3);
        }
    }
    __syncthreads();

    // ---- routing: 1 column per thread; k index is pair-permuted ----
    // rows[j*16 + 2i]   = u[16j+lane][go*16 + i]
    // rows[j*16 + 2i+1] = u[16j+lane][go*16 + i + 8]
    float rows[80];
#pragma unroll
    for (int j = 0; j < 5; j++) {
        int n = 16 * j + lane;
        if (n >= 72) n -= 72;            // wrap; excluded from sums, e4=0
        const uint4* rp = reinterpret_cast<const uint4*>(su2 + n * USTRIDE_P + go * 8);
        uint4 q0 = rp[0];
        uint4 q1 = rp[1];
        float2 f;
        f = __half22float2(*reinterpret_cast<__half2*>(&q0.x));
        rows[j * 16 + 0] = f.x;  rows[j * 16 + 1] = f.y;
        f = __half22float2(*reinterpret_cast<__half2*>(&q0.y));
        rows[j * 16 + 2] = f.x;  rows[j * 16 + 3] = f.y;
        f = __half22float2(*reinterpret_cast<__half2*>(&q0.z));
        rows[j * 16 + 4] = f.x;  rows[j * 16 + 5] = f.y;
        f = __half22float2(*reinterpret_cast<__half2*>(&q0.w));
        rows[j * 16 + 6] = f.x;  rows[j * 16 + 7] = f.y;
        f = __half22float2(*reinterpret_cast<__half2*>(&q1.x));
        rows[j * 16 + 8] = f.x;  rows[j * 16 + 9] = f.y;
        f = __half22float2(*reinterpret_cast<__half2*>(&q1.y));
        rows[j * 16 + 10] = f.x; rows[j * 16 + 11] = f.y;
        f = __half22float2(*reinterpret_cast<__half2*>(&q1.z));
        rows[j * 16 + 12] = f.x; rows[j * 16 + 13] = f.y;
        f = __half22float2(*reinterpret_cast<__half2*>(&q1.w));
        rows[j * 16 + 14] = f.x; rows[j * 16 + 15] = f.y;
    }

    // v0 = mean over n: local row sums (exclude wrapped row), reduce-scatter
    float a[16];
#pragma unroll
    for (int k = 0; k < 16; k++) {
        float s = ((rows[k] + rows[16 + k]) + (rows[32 + k] + rows[48 + k]));
        if (lane < 8) s += rows[64 + k];
        a[k] = s;
    }
#pragma unroll
    for (int mm = 0; mm < 4; mm++) {
        const int m = 8 >> mm;
        bool up = (lane & m) != 0;
#pragma unroll
        for (int i = 0; i < 16; i++) {
            if (i >= m) continue;
            float send = up ? a[i] : a[i + m];
            float got = __shfl_xor_sync(FULL, send, m);
            a[i] = (up ? a[i + m] : a[i]) + got;
        }
    }
    float v_own = a[0] * (1.f / 72.f);

    float vv[16];
#pragma unroll
    for (int k = 0; k < 16; k++) vv[k] = __shfl_sync(FULL, v_own, k, 16);

    float ov = 0.f;
#pragma unroll
    for (int it = 0; it < 3; it++) {
        float sq = 0.f;
#pragma unroll
        for (int k = 0; k < 16; k++) sq = fmaf(vv[k], vv[k], sq);
        float rn = rsqrtf(fmaxf(sq, 1e-24f));

        float e[5];
#pragma unroll
        for (int j = 0; j < 5; j++) {
            float d = 0.f;
#pragma unroll
            for (int k = 0; k < 16; k++) d = fmaf(rows[j * 16 + k], vv[k], d);
            e[j] = __expf(d * rn);
        }
        if (lane >= 8) e[4] = 0.f;

        float ssum = ((e[0] + e[1]) + (e[2] + e[3])) + e[4];
        ssum += __shfl_xor_sync(FULL, ssum, 8);
        ssum += __shfl_xor_sync(FULL, ssum, 4);
        ssum += __shfl_xor_sync(FULL, ssum, 2);
        ssum += __shfl_xor_sync(FULL, ssum, 1);

#pragma unroll
        for (int k = 0; k < 16; k++) {
            float acc = e[0] * rows[k];
            acc = fmaf(e[1], rows[16 + k], acc);
            acc = fmaf(e[2], rows[32 + k], acc);
            acc = fmaf(e[3], rows[48 + k], acc);
            acc = fmaf(e[4], rows[64 + k], acc);
            a[k] = acc;
        }

        // reduce-scatter: lane s ends with total a[s]
#pragma unroll
        for (int mm = 0; mm < 4; mm++) {
            const int m = 8 >> mm;
            bool up = (lane & m) != 0;
#pragma unroll
            for (int i = 0; i < 16; i++) {
                if (i >= m) continue;
                float send = up ? a[i] : a[i + m];
                float got = __shfl_xor_sync(FULL, send, m);
                a[i] = (up ? a[i + m] : a[i]) + got;
            }
        }
        float vfin = __fdividef(a[0], ssum);

        if (it < 2) {
#pragma unroll
            for (int k = 0; k < 16; k++) vv[k] = __shfl_sync(FULL, vfin, k, 16);
        } else {
            float s2 = vfin * vfin;
            s2 += __shfl_xor_sync(FULL, s2, 8);
            s2 += __shfl_xor_sync(FULL, s2, 4);
            s2 += __shfl_xor_sync(FULL, s2, 2);
            s2 += __shfl_xor_sync(FULL, s2, 1);
            float norm = sqrtf(s2);
            ov = vfin * __fdividef(norm, 1.f + s2);
        }
    }

    // output column: pair-permuted l: col = go*16 + (lane>>1) + ((lane&1)<<3)
    const int col = (go << 4) + (lane >> 1) + ((lane & 1) << 3);
    out[((b * 256 + col) * 32 + h) * 32 + w] = ov;
}

extern "C" void kernel_launch(void* const* d_in, const int* in_sizes, int n_in,
                              void* d_out, int out_size) {
    const float* x = (const float*)d_in[0];    // [2,128,32,32]
    const float* w = (const float*)d_in[1];    // [16,16,16,3,3]
    float* out = (float*)d_out;                // [2,256,32,32]

    const int smem_bytes = 1152 * 2 + 72 * USTRIDE_P * 4;   // 2304 + 38016 = 40320 B
    cudaFuncSetAttribute(capsule_kernel,
                         cudaFuncAttributeMaxDynamicSharedMemorySize, smem_bytes);

    wt_frag<<<18, 256>>>(w);
    capsule_kernel<<<2048, 256, smem_bytes>>>(x, out);
}

// round 15
// speedup vs baseline: 1.0901x; 1.0901x over previous
#include <cuda_runtime.h>
#include <cuda_fp16.h>
#include <float.h>
#include <math.h>

// CapsuleConv2d: B=2, Cin=128, H=W=32, weight [O=16,L=16,M=16,3,3]
// 1 CTA per (b,h,w), 128 threads (4 warps), 3 CTAs/SM. R13 structure.
// PRIORS ON TENSOR CORES: per p, C_p[256(ol) x 8(g)] = W_p[256x16] * XS_p[16x8]
//   m16n8k16; warp w owns ol-tiles 4w..4w+3. A-fragments precomputed (g_wfrag).
//   Epilogue stores PAIRED half2 (ol, ol+8) at permuted pair slots -> STS.32.
// ROUTING: 2 sequential passes, 1 column/thread/pass (k index pair-permuted,
//   transparent to the math). Scale-invariant iterations: unnormalized A carried,
//   ssum + division only in the final iteration. Cross-lane per iter:
//   15 (reduce-scatter) + 16 (allgather) shfl; +4 (ssum) on last iter only.

__device__ uint4 g_wfrag[9 * 16 * 32];  // [(p*16+tile)*32 + lane] = {a0,a1,a2,a3}

__global__ void wt_frag(const float* __restrict__ w) {
    int idx = blockIdx.x * 256 + threadIdx.x;   // 4608 total
    if (idx >= 4608) return;
    int p    = idx >> 9;          // 0..8
    int tile = (idx >> 5) & 15;   // ol tile
    int lane = idx & 31;
    int gid  = lane >> 2;         // row group
    int kb   = (lane & 3) * 2;    // col base (k)
    const int base = tile * 16;
    auto W = [&](int r, int k) { return w[((base + r) * 16 + k) * 9 + p]; };
    __half2 a0 = __floats2half2_rn(W(gid,     kb),     W(gid,     kb + 1));
    __half2 a1 = __floats2half2_rn(W(gid + 8, kb),     W(gid + 8, kb + 1));
    __half2 a2 = __floats2half2_rn(W(gid,     kb + 8), W(gid,     kb + 9));
    __half2 a3 = __floats2half2_rn(W(gid + 8, kb + 8), W(gid + 8, kb + 9));
    uint4 o;
    o.x = *reinterpret_cast<unsigned*>(&a0);
    o.y = *reinterpret_cast<unsigned*>(&a1);
    o.z = *reinterpret_cast<unsigned*>(&a2);
    o.w = *reinterpret_cast<unsigned*>(&a3);
    g_wfrag[idx] = o;
}

#define USTRIDE_P 132   // su row stride in half2 pairs (528 B)

__global__ __launch_bounds__(128, 3)
void capsule_kernel(const float* __restrict__ x, float* __restrict__ out) {
    extern __shared__ __align__(16) __half smemh[];
    __half* xsh = smemh;                                     // [1152] patch fp16
    __half2* su2 = reinterpret_cast<__half2*>(smemh + 1152); // [72*USTRIDE_P]

    const unsigned FULL = 0xffffffffu;
    const int tid = threadIdx.x;
    const int lane = tid & 15;       // routing lane in 16-group
    const int grp = tid >> 4;        // o for pass A (0..7)
    const int wid = tid >> 5;        // warp id (0..3)
    const int l32 = tid & 31;
    const int gid = l32 >> 2;        // mma row group
    const int kb  = (l32 & 3) * 2;   // mma k/g base
    const int bid = blockIdx.x;
    const int b = bid >> 10;
    const int h = (bid >> 5) & 31;
    const int w = bid & 31;

    // Stage 3x3 patch (zero-padded) as fp16: 9 pixels x 128 channels
    for (int idx = tid; idx < 9 * 128; idx += 128) {
        int p = idx >> 7;
        int c = idx & 127;
        int hh = h + p / 3 - 1;
        int ww = w + p % 3 - 1;
        float v = 0.f;
        if ((unsigned)hh < 32u && (unsigned)ww < 32u)
            v = x[((b * 128 + c) * 32 + hh) * 32 + ww];
        xsh[idx] = __float2half_rn(v);
    }
    __syncthreads();

    // ---- priors via tensor cores; warp handles tiles 4*wid .. 4*wid+3 ----
#pragma unroll
    for (int p = 0; p < 9; p++) {
        unsigned b0 = *reinterpret_cast<const unsigned*>(&xsh[p * 128 + gid * 16 + kb]);
        unsigned b1 = *reinterpret_cast<const unsigned*>(&xsh[p * 128 + gid * 16 + kb + 8]);
#pragma unroll
        for (int tt = 0; tt < 4; tt++) {
            int tile = wid * 4 + tt;
            uint4 af = g_wfrag[(p * 16 + tile) * 32 + l32];
            float d0, d1, d2, d3;
            asm volatile(
                "mma.sync.aligned.m16n8k16.row.col.f32.f16.f16.f32 "
                "{%0,%1,%2,%3}, {%4,%5,%6,%7}, {%8,%9}, {%10,%11,%12,%13};"
                : "=f"(d0), "=f"(d1), "=f"(d2), "=f"(d3)
                : "r"(af.x), "r"(af.y), "r"(af.z), "r"(af.w),
                  "r"(b0), "r"(b1),
                  "f"(0.f), "f"(0.f), "f"(0.f), "f"(0.f));
            // d0=(ol0, g=kb) d1=(ol0, kb+1) d2=(ol0+8, kb) d3=(ol0+8, kb+1)
            int n0 = kb * 9 + p;
            int pp = tile * 8 + gid;     // paired slot: holds (ol0, ol0+8)
            su2[n0 * USTRIDE_P + pp]       = __floats2half2_rn(d0, d2);
            su2[(n0 + 9) * USTRIDE_P + pp] = __floats2half2_rn(d1, d3);
        }
    }
    __syncthreads();

    // ---- routing: two sequential passes (go = grp, grp+8) ----
#pragma unroll 1
    for (int pass = 0; pass < 2; pass++) {
        const int go = grp + pass * 8;

        // rows[j*16+2i]   = u[16j+lane][go*16+i]
        // rows[j*16+2i+1] = u[16j+lane][go*16+i+8]   (pair-permuted k)
        float rows[80];
#pragma unroll
        for (int j = 0; j < 5; j++) {
            int n = 16 * j + lane;
            if (n >= 72) n -= 72;            // wrap; excluded from sums, e4=0
            const uint4* rp = reinterpret_cast<const uint4*>(su2 + n * USTRIDE_P + go * 8);
            uint4 q0 = rp[0];
            uint4 q1 = rp[1];
            float2 f;
            f = __half22float2(*reinterpret_cast<__half2*>(&q0.x));
            rows[j * 16 + 0] = f.x;  rows[j * 16 + 1] = f.y;
            f = __half22float2(*reinterpret_cast<__half2*>(&q0.y));
            rows[j * 16 + 2] = f.x;  rows[j * 16 + 3] = f.y;
            f = __half22float2(*reinterpret_cast<__half2*>(&q0.z));
            rows[j * 16 + 4] = f.x;  rows[j * 16 + 5] = f.y;
            f = __half22float2(*reinterpret_cast<__half2*>(&q0.w));
            rows[j * 16 + 6] = f.x;  rows[j * 16 + 7] = f.y;
            f = __half22float2(*reinterpret_cast<__half2*>(&q1.x));
            rows[j * 16 + 8] = f.x;  rows[j * 16 + 9] = f.y;
            f = __half22float2(*reinterpret_cast<__half2*>(&q1.y));
            rows[j * 16 + 10] = f.x; rows[j * 16 + 11] = f.y;
            f = __half22float2(*reinterpret_cast<__half2*>(&q1.z));
            rows[j * 16 + 12] = f.x; rows[j * 16 + 13] = f.y;
            f = __half22float2(*reinterpret_cast<__half2*>(&q1.w));
            rows[j * 16 + 14] = f.x; rows[j * 16 + 15] = f.y;
        }

        // A0 (unnormalized v direction) = row sums; reduce-scatter + allgather
        float a[16];
#pragma unroll
        for (int k = 0; k < 16; k++) {
            float s = ((rows[k] + rows[16 + k]) + (rows[32 + k] + rows[48 + k]));
            if (lane < 8) s += rows[64 + k];
            a[k] = s;
        }
#pragma unroll
        for (int mm = 0; mm < 4; mm++) {
            const int m = 8 >> mm;
            bool up = (lane & m) != 0;
#pragma unroll
            for (int i = 0; i < 16; i++) {
                if (i >= m) continue;
                float send = up ? a[i] : a[i + m];
                float got = __shfl_xor_sync(FULL, send, m);
                a[i] = (up ? a[i + m] : a[i]) + got;
            }
        }
        float A_rep[16];
#pragma unroll
        for (int k = 0; k < 16; k++) A_rep[k] = __shfl_sync(FULL, a[0], k, 16);

        float ov = 0.f;
#pragma unroll
        for (int it = 0; it < 3; it++) {
            // direction of A (scale-invariant logits)
            float s2 = 0.f;
#pragma unroll
            for (int k = 0; k < 16; k++) s2 = fmaf(A_rep[k], A_rep[k], s2);
            float rn = rsqrtf(fmaxf(s2, 1e-24f));

            float e[5];
#pragma unroll
            for (int j = 0; j < 5; j++) {
                float d = 0.f;
#pragma unroll
                for (int k = 0; k < 16; k++) d = fmaf(rows[j * 16 + k], A_rep[k], d);
                e[j] = __expf(d * rn);
            }
            if (lane >= 8) e[4] = 0.f;

            float ssum = 0.f;
            if (it == 2) {   // only the final iteration needs the softmax sum
                ssum = ((e[0] + e[1]) + (e[2] + e[3])) + e[4];
                ssum += __shfl_xor_sync(FULL, ssum, 8);
                ssum += __shfl_xor_sync(FULL, ssum, 4);
                ssum += __shfl_xor_sync(FULL, ssum, 2);
                ssum += __shfl_xor_sync(FULL, ssum, 1);
            }

#pragma unroll
            for (int k = 0; k < 16; k++) {
                float acc = e[0] * rows[k];
                acc = fmaf(e[1], rows[16 + k], acc);
                acc = fmaf(e[2], rows[32 + k], acc);
                acc = fmaf(e[3], rows[48 + k], acc);
                acc = fmaf(e[4], rows[64 + k], acc);
                a[k] = acc;
            }

            // reduce-scatter: lane s ends with total a[s]
#pragma unroll
            for (int mm = 0; mm < 4; mm++) {
                const int m = 8 >> mm;
                bool up = (lane & m) != 0;
#pragma unroll
                for (int i = 0; i < 16; i++) {
                    if (i >= m) continue;
                    float send = up ? a[i] : a[i + m];
                    float got = __shfl_xor_sync(FULL, send, m);
                    a[i] = (up ? a[i + m] : a[i]) + got;
                }
            }

            if (it < 2) {
#pragma unroll
                for (int k = 0; k < 16; k++) A_rep[k] = __shfl_sync(FULL, a[0], k, 16);
            } else {
                float vfin = __fdividef(a[0], ssum);   // true v for squash
                float q2 = vfin * vfin;
                q2 += __shfl_xor_sync(FULL, q2, 8);
                q2 += __shfl_xor_sync(FULL, q2, 4);
                q2 += __shfl_xor_sync(FULL, q2, 2);
                q2 += __shfl_xor_sync(FULL, q2, 1);
                float norm = sqrtf(q2);
                ov = vfin * __fdividef(norm, 1.f + q2);
            }
        }

        // output column: pair-permuted l
        const int col = (go << 4) + (lane >> 1) + ((lane & 1) << 3);
        out[((b * 256 + col) * 32 + h) * 32 + w] = ov;
    }
}

extern "C" void kernel_launch(void* const* d_in, const int* in_sizes, int n_in,
                              void* d_out, int out_size) {
    const float* x = (const float*)d_in[0];    // [2,128,32,32]
    const float* w = (const float*)d_in[1];    // [16,16,16,3,3]
    float* out = (float*)d_out;                // [2,256,32,32]

    const int smem_bytes = 1152 * 2 + 72 * USTRIDE_P * 4;   // 2304 + 38016 = 40320 B
    cudaFuncSetAttribute(capsule_kernel,
                         cudaFuncAttributeMaxDynamicSharedMemorySize, smem_bytes);

    wt_frag<<<18, 256>>>(w);
    capsule_kernel<<<2048, 128, smem_bytes>>>(x, out);
}

// round 17
// speedup vs baseline: 1.1064x; 1.0149x over previous
#include <cuda_runtime.h>
#include <cuda_fp16.h>
#include <float.h>
#include <math.h>

// CapsuleConv2d: B=2, Cin=128, H=W=32, weight [O=16,L=16,M=16,3,3]
// 1 CTA per (b,h,w), 128 threads (4 warps), 4 CTAs/SM (regs 116 < 128 -> no spill).
// PRIORS ON TENSOR CORES: per p, C_p[256(ol) x 8(g)] = W_p[256x16] * XS_p[16x8]
//   m16n8k16; warp w owns ol-tiles 4w..4w+3. A-fragments precomputed (g_wfrag).
//   Epilogue stores PAIRED half2 (ol, ol+8) at permuted pair slots -> STS.32.
// ROUTING: 2 sequential passes, 1 column/thread/pass (k index pair-permuted,
//   transparent to the math). Scale-invariant iterations: unnormalized A carried,
//   ssum + division only in the final iteration.

__device__ uint4 g_wfrag[9 * 16 * 32];  // [(p*16+tile)*32 + lane] = {a0,a1,a2,a3}

__global__ void wt_frag(const float* __restrict__ w) {
    int idx = blockIdx.x * 256 + threadIdx.x;   // 4608 total
    if (idx >= 4608) return;
    int p    = idx >> 9;          // 0..8
    int tile = (idx >> 5) & 15;   // ol tile
    int lane = idx & 31;
    int gid  = lane >> 2;         // row group
    int kb   = (lane & 3) * 2;    // col base (k)
    const int base = tile * 16;
    auto W = [&](int r, int k) { return w[((base + r) * 16 + k) * 9 + p]; };
    __half2 a0 = __floats2half2_rn(W(gid,     kb),     W(gid,     kb + 1));
    __half2 a1 = __floats2half2_rn(W(gid + 8, kb),     W(gid + 8, kb + 1));
    __half2 a2 = __floats2half2_rn(W(gid,     kb + 8), W(gid,     kb + 9));
    __half2 a3 = __floats2half2_rn(W(gid + 8, kb + 8), W(gid + 8, kb + 9));
    uint4 o;
    o.x = *reinterpret_cast<unsigned*>(&a0);
    o.y = *reinterpret_cast<unsigned*>(&a1);
    o.z = *reinterpret_cast<unsigned*>(&a2);
    o.w = *reinterpret_cast<unsigned*>(&a3);
    g_wfrag[idx] = o;
}

#define USTRIDE_P 132   // su row stride in half2 pairs (528 B)

__global__ __launch_bounds__(128, 4)
void capsule_kernel(const float* __restrict__ x, float* __restrict__ out) {
    extern __shared__ __align__(16) __half smemh[];
    __half* xsh = smemh;                                     // [1152] patch fp16
    __half2* su2 = reinterpret_cast<__half2*>(smemh + 1152); // [72*USTRIDE_P]

    const unsigned FULL = 0xffffffffu;
    const int tid = threadIdx.x;
    const int lane = tid & 15;       // routing lane in 16-group
    const int grp = tid >> 4;        // o for pass A (0..7)
    const int wid = tid >> 5;        // warp id (0..3)
    const int l32 = tid & 31;
    const int gid = l32 >> 2;        // mma row group
    const int kb  = (l32 & 3) * 2;   // mma k/g base
    const int bid = blockIdx.x;
    const int b = bid >> 10;
    const int h = (bid >> 5) & 31;
    const int w = bid & 31;

    // Stage 3x3 patch (zero-padded) as fp16: 9 pixels x 128 channels
    for (int idx = tid; idx < 9 * 128; idx += 128) {
        int p = idx >> 7;
        int c = idx & 127;
        int hh = h + p / 3 - 1;
        int ww = w + p % 3 - 1;
        float v = 0.f;
        if ((unsigned)hh < 32u && (unsigned)ww < 32u)
            v = x[((b * 128 + c) * 32 + hh) * 32 + ww];
        xsh[idx] = __float2half_rn(v);
    }
    __syncthreads();

    // ---- priors via tensor cores; warp handles tiles 4*wid .. 4*wid+3 ----
#pragma unroll
    for (int p = 0; p < 9; p++) {
        unsigned b0 = *reinterpret_cast<const unsigned*>(&xsh[p * 128 + gid * 16 + kb]);
        unsigned b1 = *reinterpret_cast<const unsigned*>(&xsh[p * 128 + gid * 16 + kb + 8]);
#pragma unroll
        for (int tt = 0; tt < 4; tt++) {
            int tile = wid * 4 + tt;
            uint4 af = g_wfrag[(p * 16 + tile) * 32 + l32];
            float d0, d1, d2, d3;
            asm volatile(
                "mma.sync.aligned.m16n8k16.row.col.f32.f16.f16.f32 "
                "{%0,%1,%2,%3}, {%4,%5,%6,%7}, {%8,%9}, {%10,%11,%12,%13};"
                : "=f"(d0), "=f"(d1), "=f"(d2), "=f"(d3)
                : "r"(af.x), "r"(af.y), "r"(af.z), "r"(af.w),
                  "r"(b0), "r"(b1),
                  "f"(0.f), "f"(0.f), "f"(0.f), "f"(0.f));
            // d0=(ol0, g=kb) d1=(ol0, kb+1) d2=(ol0+8, kb) d3=(ol0+8, kb+1)
            int n0 = kb * 9 + p;
            int pp = tile * 8 + gid;     // paired slot: holds (ol0, ol0+8)
            su2[n0 * USTRIDE_P + pp]       = __floats2half2_rn(d0, d2);
            su2[(n0 + 9) * USTRIDE_P + pp] = __floats2half2_rn(d1, d3);
        }
    }
    __syncthreads();

    // ---- routing: two sequential passes (go = grp, grp+8) ----
#pragma unroll 1
    for (int pass = 0; pass < 2; pass++) {
        const int go = grp + pass * 8;

        // rows[j*16+2i]   = u[16j+lane][go*16+i]
        // rows[j*16+2i+1] = u[16j+lane][go*16+i+8]   (pair-permuted k)
        float rows[80];
#pragma unroll
        for (int j = 0; j < 5; j++) {
            int n = 16 * j + lane;
            if (n >= 72) n -= 72;            // wrap; excluded from sums, e4=0
            const uint4* rp = reinterpret_cast<const uint4*>(su2 + n * USTRIDE_P + go * 8);
            uint4 q0 = rp[0];
            uint4 q1 = rp[1];
            float2 f;
            f = __half22float2(*reinterpret_cast<__half2*>(&q0.x));
            rows[j * 16 + 0] = f.x;  rows[j * 16 + 1] = f.y;
            f = __half22float2(*reinterpret_cast<__half2*>(&q0.y));
            rows[j * 16 + 2] = f.x;  rows[j * 16 + 3] = f.y;
            f = __half22float2(*reinterpret_cast<__half2*>(&q0.z));
            rows[j * 16 + 4] = f.x;  rows[j * 16 + 5] = f.y;
            f = __half22float2(*reinterpret_cast<__half2*>(&q0.w));
            rows[j * 16 + 6] = f.x;  rows[j * 16 + 7] = f.y;
            f = __half22float2(*reinterpret_cast<__half2*>(&q1.x));
            rows[j * 16 + 8] = f.x;  rows[j * 16 + 9] = f.y;
            f = __half22float2(*reinterpret_cast<__half2*>(&q1.y));
            rows[j * 16 + 10] = f.x; rows[j * 16 + 11] = f.y;
            f = __half22float2(*reinterpret_cast<__half2*>(&q1.z));
            rows[j * 16 + 12] = f.x; rows[j * 16 + 13] = f.y;
            f = __half22float2(*reinterpret_cast<__half2*>(&q1.w));
            rows[j * 16 + 14] = f.x; rows[j * 16 + 15] = f.y;
        }

        // A0 (unnormalized v direction) = row sums; reduce-scatter + allgather
        float a[16];
#pragma unroll
        for (int k = 0; k < 16; k++) {
            float s = ((rows[k] + rows[16 + k]) + (rows[32 + k] + rows[48 + k]));
            if (lane < 8) s += rows[64 + k];
            a[k] = s;
        }
#pragma unroll
        for (int mm = 0; mm < 4; mm++) {
            const int m = 8 >> mm;
            bool up = (lane & m) != 0;
#pragma unroll
            for (int i = 0; i < 16; i++) {
                if (i >= m) continue;
                float send = up ? a[i] : a[i + m];
                float got = __shfl_xor_sync(FULL, send, m);
                a[i] = (up ? a[i + m] : a[i]) + got;
            }
        }
        float A_rep[16];
#pragma unroll
        for (int k = 0; k < 16; k++) A_rep[k] = __shfl_sync(FULL, a[0], k, 16);

        float ov = 0.f;
#pragma unroll
        for (int it = 0; it < 3; it++) {
            // direction of A (scale-invariant logits)
            float s2 = 0.f;
#pragma unroll
            for (int k = 0; k < 16; k++) s2 = fmaf(A_rep[k], A_rep[k], s2);
            float rn = rsqrtf(fmaxf(s2, 1e-24f));

            float e[5];
#pragma unroll
            for (int j = 0; j < 5; j++) {
                float d = 0.f;
#pragma unroll
                for (int k = 0; k < 16; k++) d = fmaf(rows[j * 16 + k], A_rep[k], d);
                e[j] = __expf(d * rn);
            }
            if (lane >= 8) e[4] = 0.f;

            float ssum = 0.f;
            if (it == 2) {   // only the final iteration needs the softmax sum
                ssum = ((e[0] + e[1]) + (e[2] + e[3])) + e[4];
                ssum += __shfl_xor_sync(FULL, ssum, 8);
                ssum += __shfl_xor_sync(FULL, ssum, 4);
                ssum += __shfl_xor_sync(FULL, ssum, 2);
                ssum += __shfl_xor_sync(FULL, ssum, 1);
            }

#pragma unroll
            for (int k = 0; k < 16; k++) {
                float acc = e[0] * rows[k];
                acc = fmaf(e[1], rows[16 + k], acc);
                acc = fmaf(e[2], rows[32 + k], acc);
                acc = fmaf(e[3], rows[48 + k], acc);
                acc = fmaf(e[4], rows[64 + k], acc);
                a[k] = acc;
            }

            // reduce-scatter: lane s ends with total a[s]
#pragma unroll
            for (int mm = 0; mm < 4; mm++) {
                const int m = 8 >> mm;
                bool up = (lane & m) != 0;
#pragma unroll
                for (int i = 0; i < 16; i++) {
                    if (i >= m) continue;
                    float send = up ? a[i] : a[i + m];
                    float got = __shfl_xor_sync(FULL, send, m);
                    a[i] = (up ? a[i + m] : a[i]) + got;
                }
            }

            if (it < 2) {
#pragma unroll
                for (int k = 0; k < 16; k++) A_rep[k] = __shfl_sync(FULL, a[0], k, 16);
            } else {
                float vfin = __fdividef(a[0], ssum);   // true v for squash
                float q2 = vfin * vfin;
                q2 += __shfl_xor_sync(FULL, q2, 8);
                q2 += __shfl_xor_sync(FULL, q2, 4);
                q2 += __shfl_xor_sync(FULL, q2, 2);
                q2 += __shfl_xor_sync(FULL, q2, 1);
                float norm = sqrtf(q2);
                ov = vfin * __fdividef(norm, 1.f + q2);
            }
        }

        // output column: pair-permuted l
        const int col = (go << 4) + (lane >> 1) + ((lane & 1) << 3);
        out[((b * 256 + col) * 32 + h) * 32 + w] = ov;
    }
}

extern "C" void kernel_launch(void* const* d_in, const int* in_sizes, int n_in,
                              void* d_out, int out_size) {
    const float* x = (const float*)d_in[0];    // [2,128,32,32]
    const float* w = (const float*)d_in[1];    // [16,16,16,3,3]
    float* out = (float*)d_out;                // [2,256,32,32]

    const int smem_bytes = 1152 * 2 + 72 * USTRIDE_P * 4;   // 2304 + 38016 = 40320 B
    cudaFuncSetAttribute(capsule_kernel,
                         cudaFuncAttributeMaxDynamicSharedMemorySize, smem_bytes);

    wt_frag<<<18, 256>>>(w);
    capsule_kernel<<<2048, 128, smem_bytes>>>(x, out);
}